// round 2
// baseline (speedup 1.0000x reference)
#include <cuda_runtime.h>
#include <stdint.h>

// Problem constants (match reference: B=1048576, Z_DIM=128, K=512)
#define ZDIM 128
#define KDIM 512

// Scratch for transposed a: at[k][d] = a[d][k].  512*128 floats = 256 KB.
__device__ float g_at[KDIM * ZDIM];

// ---------------------------------------------------------------------------
// Pre-pass: transpose a (ZDIM x KDIM row-major) -> g_at (KDIM x ZDIM row-major)
// so the per-row gather becomes a contiguous, coalesced 512B read that stays
// resident in L2 (256 KB total).
// ---------------------------------------------------------------------------
__global__ void transpose_a_kernel(const float* __restrict__ a) {
    int tid = blockIdx.x * blockDim.x + threadIdx.x;   // 0 .. K*Z-1
    if (tid >= KDIM * ZDIM) return;
    int k = tid / ZDIM;      // consecutive tids share k -> coalesced write
    int d = tid % ZDIM;
    g_at[tid] = a[d * KDIM + k];   // strided read (fine; tiny tensor, one pass)
}

// ---------------------------------------------------------------------------
// Main kernel: warp-per-row. 32 lanes x float4 = 128 floats = one row.
//   out[b] = z[b] + at[idx[b]] * scale[b]
// z/out: fully coalesced 512B per warp. at row: coalesced 512B, L2-hit.
// NOTE: labels_idx is int32 on device (JAX x64 disabled demotes int64->int32).
// ---------------------------------------------------------------------------
__global__ void __launch_bounds__(256, 8)
fused_gather_axpy_kernel(const float4* __restrict__ z4,
                         const int* __restrict__ labels_idx,
                         const float* __restrict__ labels_scale,
                         float4* __restrict__ out4,
                         int n_rows) {
    const int lane = threadIdx.x & 31;
    const int warp = (blockIdx.x * (blockDim.x >> 5)) + (threadIdx.x >> 5);
    if (warp >= n_rows) return;

    // Broadcast loads (same address across warp -> single transaction)
    const int   idx = labels_idx[warp];
    const float s   = labels_scale[warp];

    const float4* __restrict__ at4 =
        reinterpret_cast<const float4*>(g_at) + (size_t)idx * (ZDIM / 4);

    const size_t off = (size_t)warp * (ZDIM / 4) + lane;
    float4 zv = z4[off];
    float4 av = at4[lane];

    float4 o;
    o.x = fmaf(av.x, s, zv.x);
    o.y = fmaf(av.y, s, zv.y);
    o.z = fmaf(av.z, s, zv.z);
    o.w = fmaf(av.w, s, zv.w);

    out4[off] = o;
}

extern "C" void kernel_launch(void* const* d_in, const int* in_sizes, int n_in,
                              void* d_out, int out_size) {
    const float* z     = (const float*)d_in[0];   // (B, 128) f32
    const float* a     = (const float*)d_in[1];   // (128, 512) f32
    const int*   idx   = (const int*)d_in[2];     // (B,) int32 on device
    const float* scale = (const float*)d_in[3];   // (B,) f32
    float*       out   = (float*)d_out;

    const int B = in_sizes[2];   // number of rows (labels count)

    // 1) transpose a into L2-resident scratch
    {
        int n = KDIM * ZDIM;
        transpose_a_kernel<<<(n + 255) / 256, 256>>>(a);
    }

    // 2) fused gather + axpy, warp per row (8 rows per 256-thread block)
    {
        int warps_per_block = 256 / 32;
        int blocks = (B + warps_per_block - 1) / warps_per_block;
        fused_gather_axpy_kernel<<<blocks, 256>>>(
            (const float4*)z, idx, scale, (float4*)out, B);
    }
}

// round 3
// speedup vs baseline: 1.0177x; 1.0177x over previous
#include <cuda_runtime.h>
#include <stdint.h>

// Problem constants (match reference: B=1048576, Z_DIM=128, K=512)
#define ZDIM 128
#define KDIM 512

// Scratch for transposed a: at[k][d] = a[d][k].  512*128 floats = 256 KB.
__device__ float g_at[KDIM * ZDIM];

// ---------------------------------------------------------------------------
// Pre-pass: transpose a (ZDIM x KDIM row-major) -> g_at (KDIM x ZDIM row-major)
// so the per-row gather becomes a contiguous, coalesced 512B read that stays
// resident in L2 (256 KB total).
// ---------------------------------------------------------------------------
__global__ void transpose_a_kernel(const float* __restrict__ a) {
    int tid = blockIdx.x * blockDim.x + threadIdx.x;   // 0 .. K*Z-1
    if (tid >= KDIM * ZDIM) return;
    int k = tid / ZDIM;      // consecutive tids share k -> coalesced write
    int d = tid % ZDIM;
    g_at[tid] = a[d * KDIM + k];   // strided read (fine; tiny tensor, one pass)
}

// ---------------------------------------------------------------------------
// Main kernel: warp-per-row. 32 lanes x float4 = 128 floats = one row.
//   out[b] = z[b] + at[idx[b]] * scale[b]
// z/out: fully coalesced 512B per warp. at row: coalesced 512B, L2-hit.
// NOTE: labels_idx is int32 on device (JAX x64 disabled demotes int64->int32).
// ---------------------------------------------------------------------------
__global__ void __launch_bounds__(256, 8)
fused_gather_axpy_kernel(const float4* __restrict__ z4,
                         const int* __restrict__ labels_idx,
                         const float* __restrict__ labels_scale,
                         float4* __restrict__ out4,
                         int n_rows) {
    const int lane = threadIdx.x & 31;
    const int warp = (blockIdx.x * (blockDim.x >> 5)) + (threadIdx.x >> 5);
    if (warp >= n_rows) return;

    // Broadcast loads (same address across warp -> single transaction)
    const int   idx = labels_idx[warp];
    const float s   = labels_scale[warp];

    const float4* __restrict__ at4 =
        reinterpret_cast<const float4*>(g_at) + (size_t)idx * (ZDIM / 4);

    const size_t off = (size_t)warp * (ZDIM / 4) + lane;
    float4 zv = z4[off];
    float4 av = at4[lane];

    float4 o;
    o.x = fmaf(av.x, s, zv.x);
    o.y = fmaf(av.y, s, zv.y);
    o.z = fmaf(av.z, s, zv.z);
    o.w = fmaf(av.w, s, zv.w);

    out4[off] = o;
}

extern "C" void kernel_launch(void* const* d_in, const int* in_sizes, int n_in,
                              void* d_out, int out_size) {
    const float* z     = (const float*)d_in[0];   // (B, 128) f32
    const float* a     = (const float*)d_in[1];   // (128, 512) f32
    const int*   idx   = (const int*)d_in[2];     // (B,) int32 on device
    const float* scale = (const float*)d_in[3];   // (B,) f32
    float*       out   = (float*)d_out;

    const int B = in_sizes[2];   // number of rows (labels count)

    // 1) transpose a into L2-resident scratch
    {
        int n = KDIM * ZDIM;
        transpose_a_kernel<<<(n + 255) / 256, 256>>>(a);
    }

    // 2) fused gather + axpy, warp per row (8 rows per 256-thread block)
    {
        int warps_per_block = 256 / 32;
        int blocks = (B + warps_per_block - 1) / warps_per_block;
        fused_gather_axpy_kernel<<<blocks, 256>>>(
            (const float4*)z, idx, scale, (float4*)out, B);
    }
}